// round 5
// baseline (speedup 1.0000x reference)
#include <cuda_runtime.h>
#include <cuda_bf16.h>
#include <cstdint>

// Problem constants (shapes fixed by the dataset)
#define N_NODE   50000
#define N_EDGE   800000
#define F_IN     128
#define EDGE_DIM 16
#define HEADS    4
#define D_OUT    32
#define HD       (HEADS * D_OUT)   // 128

// ---------------- scratch (device globals; no runtime allocation) ----------
__device__ float g_xl [(size_t)N_NODE * HD];     // 25.6 MB
__device__ float g_xr [(size_t)N_NODE * HD];     // 25.6 MB
__device__ float g_sum[(size_t)N_NODE * HEADS];  //  0.8 MB
__device__ float g_agg[(size_t)N_NODE * HD];     // 25.6 MB

// ---------------- zero init --------------------------------------------------
__global__ void zero_kernel(int n_agg, int n_sum) {
    int i = blockIdx.x * blockDim.x + threadIdx.x;
    if (i < n_agg) g_agg[i] = 0.f;
    if (i < n_sum) g_sum[i] = 0.f;
}

// ---------------- projection GEMM: x_l / x_r = nodes @ W ------------------
// C[M,128] = A[M,128] @ W[128,128], two weight matrices via blockIdx.y.
// 64x64 tile, BK=16, 256 threads, 4x4 microtile, float4 global loads.
#define BM 64
#define BN 64
#define BK 16
__global__ __launch_bounds__(256) void gemm_kernel(
    const float* __restrict__ A,
    const float* __restrict__ Wl,
    const float* __restrict__ Wr,
    int M)
{
    const int byi = blockIdx.y;                 // 0..3
    const float* B = (byi < 2) ? Wl : Wr;
    float*       C = (byi < 2) ? g_xl : g_xr;
    const int cn0 = (byi & 1) * BN;
    const int rm0 = blockIdx.x * BM;

    __shared__ float As[BK][BM + 4];            // transposed, padded
    __shared__ float Bs[BK][BN];

    float acc[4][4];
#pragma unroll
    for (int i = 0; i < 4; i++)
#pragma unroll
        for (int j = 0; j < 4; j++) acc[i][j] = 0.f;

    const int tid = threadIdx.x;
    const int tx = tid & 15;
    const int ty = tid >> 4;

    const int li = tid * 4;
    const int ar = li / BK, ak = li % BK;       // A: 64 rows x 16 k
    const int bk = li / BN, bj = li % BN;       // B: 16 k x 64 cols

    for (int k0 = 0; k0 < F_IN; k0 += BK) {
        float4 av = make_float4(0.f, 0.f, 0.f, 0.f);
        if (rm0 + ar < M)
            av = *(const float4*)&A[(size_t)(rm0 + ar) * F_IN + k0 + ak];
        As[ak][ar]     = av.x;
        As[ak + 1][ar] = av.y;
        As[ak + 2][ar] = av.z;
        As[ak + 3][ar] = av.w;
        float4 bv = *(const float4*)&B[(size_t)(k0 + bk) * HD + cn0 + bj];
        *(float4*)&Bs[bk][bj] = bv;
        __syncthreads();
#pragma unroll
        for (int k = 0; k < BK; k++) {
            float4 ra = *(const float4*)&As[k][ty * 4];
            float4 rb = *(const float4*)&Bs[k][tx * 4];
            float a_[4] = {ra.x, ra.y, ra.z, ra.w};
            float b_[4] = {rb.x, rb.y, rb.z, rb.w};
#pragma unroll
            for (int i = 0; i < 4; i++)
#pragma unroll
                for (int j = 0; j < 4; j++)
                    acc[i][j] = fmaf(a_[i], b_[j], acc[i][j]);
        }
        __syncthreads();
    }
#pragma unroll
    for (int i = 0; i < 4; i++) {
        int r = rm0 + ty * 4 + i;
        if (r < M) {
            float4 v = make_float4(acc[i][0], acc[i][1], acc[i][2], acc[i][3]);
            *(float4*)&C[(size_t)r * HD + cn0 + tx * 4] = v;
        }
    }
}

// ---------------- fused edge pass: score + UNNORMALIZED aggregation --------
// One warp per edge (persistent grid, warp-strided). Lane ln owns the 4
// contiguous columns c0=4*ln..4*ln+3; head h = ln>>3. W_e columns live in
// REGISTERS (64 floats/lane, loaded once per block) — no shared memory in
// the hot loop, which removes the smem-crossbar bottleneck. Edge features
// come in as 4 warp-broadcast float4 loads. Accumulates exp_e * x_l[s]
// into g_agg (red.v4) and exp_e into g_sum; normalization in finalize.
__global__ __launch_bounds__(256) void edge_fused_kernel(
    const int*   __restrict__ snd,
    const int*   __restrict__ rcv,
    const float* __restrict__ eattr,
    const float* __restrict__ We,
    const float* __restrict__ attn,
    int E)
{
    const int tid = threadIdx.x;
    const int ln = tid & 31;
    const int c0 = ln * 4;
    const int h  = ln >> 3;

    // per-lane weight columns in registers
    float4 wr[EDGE_DIM];
#pragma unroll
    for (int k = 0; k < EDGE_DIM; k++)
        wr[k] = *(const float4*)&We[k * HD + c0];
    const float4 at4 = *(const float4*)&attn[c0];

    const int warps_total = gridDim.x * (blockDim.x >> 5);
    const int warp_id = blockIdx.x * (blockDim.x >> 5) + (tid >> 5);

    for (int e = warp_id; e < E; e += warps_total) {
        const int s = __ldg(&snd[e]);
        const int r = __ldg(&rcv[e]);

        // broadcast loads of the 16 edge features (same addr across warp)
        const float4* ea = (const float4*)(eattr + (size_t)e * EDGE_DIM);
        const float4 a0 = __ldg(ea + 0);
        const float4 a1 = __ldg(ea + 1);
        const float4 a2 = __ldg(ea + 2);
        const float4 a3 = __ldg(ea + 3);

        float4 xl = *(const float4*)(g_xl + (size_t)s * HD + c0);
        float4 xr = *(const float4*)(g_xr + (size_t)r * HD + c0);

        float4 ep;
        ep.x = a0.x * wr[0].x; ep.y = a0.x * wr[0].y;
        ep.z = a0.x * wr[0].z; ep.w = a0.x * wr[0].w;
        const float af[15] = {a0.y, a0.z, a0.w,
                              a1.x, a1.y, a1.z, a1.w,
                              a2.x, a2.y, a2.z, a2.w,
                              a3.x, a3.y, a3.z, a3.w};
#pragma unroll
        for (int k = 0; k < 15; k++) {
            ep.x = fmaf(af[k], wr[k + 1].x, ep.x);
            ep.y = fmaf(af[k], wr[k + 1].y, ep.y);
            ep.z = fmaf(af[k], wr[k + 1].z, ep.z);
            ep.w = fmaf(af[k], wr[k + 1].w, ep.w);
        }

        float m0 = xl.x + xr.x + ep.x;
        float m1 = xl.y + xr.y + ep.y;
        float m2 = xl.z + xr.z + ep.z;
        float m3 = xl.w + xr.w + ep.w;
        // leaky_relu slope 0.2
        m0 = fmaxf(m0, 0.f) + 0.2f * fminf(m0, 0.f);
        m1 = fmaxf(m1, 0.f) + 0.2f * fminf(m1, 0.f);
        m2 = fmaxf(m2, 0.f) + 0.2f * fminf(m2, 0.f);
        m3 = fmaxf(m3, 0.f) + 0.2f * fminf(m3, 0.f);

        float p = fmaf(m0, at4.x, fmaf(m1, at4.y, fmaf(m2, at4.z, m3 * at4.w)));
        // 8-lane segmented reduce -> per-head logit
        p += __shfl_xor_sync(0xffffffffu, p, 4);
        p += __shfl_xor_sync(0xffffffffu, p, 2);
        p += __shfl_xor_sync(0xffffffffu, p, 1);

        // No max-subtraction: |logit| bounded (~12), exp safe in fp32;
        // exp(l)/sum(exp(l)) == softmax exactly.
        float ev = __expf(p);

        float* dst = g_agg + (size_t)r * HD + c0;
        asm volatile("red.global.add.v4.f32 [%0], {%1, %2, %3, %4};"
                     :: "l"(dst), "f"(xl.x * ev), "f"(xl.y * ev),
                        "f"(xl.z * ev), "f"(xl.w * ev)
                     : "memory");
        if ((ln & 7) == 0)
            atomicAdd(&g_sum[(size_t)r * HEADS + h], ev);
    }
}

// ---------------- finalize: normalize + head mean ---------------------------
__global__ void finalize_kernel(float* __restrict__ out, int N) {
    int i = blockIdx.x * blockDim.x + threadIdx.x;   // over N * 32
    if (i >= N * D_OUT) return;
    int n = i >> 5, d = i & 31;
    const float* a = g_agg + (size_t)n * HD + d;
    const float* sm = g_sum + (size_t)n * HEADS;
    float v = a[0]  / (sm[0] + 1e-8f)
            + a[32] / (sm[1] + 1e-8f)
            + a[64] / (sm[2] + 1e-8f)
            + a[96] / (sm[3] + 1e-8f);
    out[i] = 0.25f * v;
}

// ---------------- launch -----------------------------------------------------
extern "C" void kernel_launch(void* const* d_in, const int* in_sizes, int n_in,
                              void* d_out, int out_size)
{
    const float* nodes = (const float*)d_in[0];
    const int*   snd   = (const int*)  d_in[1];
    const int*   rcv   = (const int*)  d_in[2];
    const float* eattr = (const float*)d_in[3];
    // Defend against the n_node scalar being present (size-1 input) or absent.
    int wbase = (in_sizes[4] == 1) ? 5 : 4;
    const float* Wl   = (const float*)d_in[wbase + 0];
    const float* Wr   = (const float*)d_in[wbase + 1];
    const float* We   = (const float*)d_in[wbase + 2];
    const float* attn = (const float*)d_in[wbase + 3];

    const int N = in_sizes[0] / F_IN;
    const int E = in_sizes[1];

    zero_kernel<<<(N * HD + 255) / 256, 256>>>(N * HD, N * HEADS);

    dim3 gg((N + BM - 1) / BM, 4);
    gemm_kernel<<<gg, 256>>>(nodes, Wl, Wr, N);

    // persistent grid, warp-strided over edges
    edge_fused_kernel<<<592, 256>>>(snd, rcv, eattr, We, attn, E);
    finalize_kernel<<<(N * D_OUT + 255) / 256, 256>>>((float*)d_out, N);
}

// round 7
// speedup vs baseline: 1.6971x; 1.6971x over previous
#include <cuda_runtime.h>
#include <cuda_bf16.h>
#include <cstdint>

// Problem constants (shapes fixed by the dataset)
#define N_NODE   50000
#define N_EDGE   800000
#define F_IN     128
#define EDGE_DIM 16
#define HEADS    4
#define D_OUT    32
#define HD       (HEADS * D_OUT)   // 128

// ---------------- scratch (device globals; no runtime allocation) ----------
__device__ float g_xl [(size_t)N_NODE * HD];     // 25.6 MB
__device__ float g_xr [(size_t)N_NODE * HD];     // 25.6 MB
__device__ float g_sum[(size_t)N_NODE * HEADS];  //  0.8 MB
__device__ float g_agg[(size_t)N_NODE * HD];     // 25.6 MB

// ---------------- zero init --------------------------------------------------
__global__ void zero_kernel(int n_agg, int n_sum) {
    int i = blockIdx.x * blockDim.x + threadIdx.x;
    if (i < n_agg) g_agg[i] = 0.f;
    if (i < n_sum) g_sum[i] = 0.f;
}

// ---------------- projection GEMM (round-2 version, BK=8) ------------------
#define BM 64
#define BN 64
#define BK 8
__global__ __launch_bounds__(256) void gemm_kernel(
    const float* __restrict__ A,
    const float* __restrict__ Wl,
    const float* __restrict__ Wr,
    int M)
{
    const int byi = blockIdx.y;                 // 0..3
    const float* B = (byi < 2) ? Wl : Wr;
    float*       C = (byi < 2) ? g_xl : g_xr;
    const int cn0 = (byi & 1) * BN;
    const int rm0 = blockIdx.x * BM;

    __shared__ float As[BK][BM + 4];
    __shared__ float Bs[BK][BN];

    float acc[4][4];
#pragma unroll
    for (int i = 0; i < 4; i++)
#pragma unroll
        for (int j = 0; j < 4; j++) acc[i][j] = 0.f;

    const int tid = threadIdx.x;
    const int tx = tid & 15;
    const int ty = tid >> 4;

    const int li = tid * 2;
    const int ar = li / BK, ak = li % BK;
    const int bk = li / BN, bj = li % BN;

    for (int k0 = 0; k0 < F_IN; k0 += BK) {
        float2 av = make_float2(0.f, 0.f);
        if (rm0 + ar < M)
            av = *(const float2*)&A[(size_t)(rm0 + ar) * F_IN + k0 + ak];
        As[ak][ar]     = av.x;
        As[ak + 1][ar] = av.y;
        float2 bv = *(const float2*)&B[(size_t)(k0 + bk) * HD + cn0 + bj];
        Bs[bk][bj]     = bv.x;
        Bs[bk][bj + 1] = bv.y;
        __syncthreads();
#pragma unroll
        for (int k = 0; k < BK; k++) {
            float4 ra = *(const float4*)&As[k][ty * 4];
            float4 rb = *(const float4*)&Bs[k][tx * 4];
            float a_[4] = {ra.x, ra.y, ra.z, ra.w};
            float b_[4] = {rb.x, rb.y, rb.z, rb.w};
#pragma unroll
            for (int i = 0; i < 4; i++)
#pragma unroll
                for (int j = 0; j < 4; j++)
                    acc[i][j] = fmaf(a_[i], b_[j], acc[i][j]);
        }
        __syncthreads();
    }
#pragma unroll
    for (int i = 0; i < 4; i++) {
        int r = rm0 + ty * 4 + i;
        if (r < M) {
            float4 v = make_float4(acc[i][0], acc[i][1], acc[i][2], acc[i][3]);
            *(float4*)&C[(size_t)r * HD + cn0 + tx * 4] = v;
        }
    }
}

// ---------------- fused edge pass: 4 edges/warp, amortized smem weights ----
// Lane ln owns columns c0=4*ln..4*ln+3 (head h = ln>>3). Each warp processes
// 4 consecutive edges per iteration so each k-slice of W_e is loaded from
// smem ONCE (1 LDS.128) and applied to all 4 edges -> 4x less smem-crossbar
// traffic than one-edge-per-warp. Edge features are loaded cooperatively
// (lane ln holds float2 = dims {2ln%16, +1} of edge ln/8) and distributed
// via shuffles. Accumulates exp_e * x_l[s] into g_agg (red.v4) and exp_e
// into g_sum; normalization happens in finalize.
__global__ __launch_bounds__(256) void edge_fused_kernel(
    const int*   __restrict__ snd,
    const int*   __restrict__ rcv,
    const float* __restrict__ eattr,
    const float* __restrict__ We,
    const float* __restrict__ attn,
    int E)
{
    __shared__ float we_s[EDGE_DIM * HD];  // 8 KB
    __shared__ float at_s[HD];
    const int tid = threadIdx.x;
    for (int i = tid; i < EDGE_DIM * HD; i += 256) we_s[i] = We[i];
    if (tid < HD) at_s[tid] = attn[tid];
    __syncthreads();

    const int ln = tid & 31;
    const int c0 = ln * 4;
    const int h  = ln >> 3;
    const float4 at4 = *(const float4*)&at_s[c0];

    const int warps_total = gridDim.x * (blockDim.x >> 5);
    const int warp_id = blockIdx.x * (blockDim.x >> 5) + (tid >> 5);

    for (int e0 = warp_id * 4; e0 < E; e0 += warps_total * 4) {
        // 4 consecutive edges (E is a multiple of 4; e0 is 16B-aligned)
        const int4 s4 = *(const int4*)&snd[e0];
        const int4 r4 = *(const int4*)&rcv[e0];
        const int ss[4] = {s4.x, s4.y, s4.z, s4.w};
        const int rr[4] = {r4.x, r4.y, r4.z, r4.w};

        // cooperative edge-feature load: 4 edges x 16 dims = 64 floats,
        // lane ln gets float2 at flat offset 2*ln (edge = ln/8, dim = 2ln%16)
        const float2 myea = *(const float2*)&eattr[(size_t)e0 * EDGE_DIM + 2 * ln];

        // gathers (the dominant memory cost; 4 independent -> good MLP)
        float4 xl[4], xr[4];
#pragma unroll
        for (int j = 0; j < 4; j++) {
            xl[j] = *(const float4*)(g_xl + (size_t)ss[j] * HD + c0);
            xr[j] = *(const float4*)(g_xr + (size_t)rr[j] * HD + c0);
        }

        // edge projection: one weight load per k, reused across 4 edges
        float4 ep[4];
#pragma unroll
        for (int j = 0; j < 4; j++) ep[j] = make_float4(0.f, 0.f, 0.f, 0.f);
#pragma unroll
        for (int k = 0; k < EDGE_DIM; k++) {
            const float4 w = *(const float4*)&we_s[k * HD + c0];
#pragma unroll
            for (int j = 0; j < 4; j++) {
                const int src = j * 8 + (k >> 1);
                const float a = (k & 1)
                    ? __shfl_sync(0xffffffffu, myea.y, src)
                    : __shfl_sync(0xffffffffu, myea.x, src);
                ep[j].x = fmaf(a, w.x, ep[j].x);
                ep[j].y = fmaf(a, w.y, ep[j].y);
                ep[j].z = fmaf(a, w.z, ep[j].z);
                ep[j].w = fmaf(a, w.w, ep[j].w);
            }
        }

#pragma unroll
        for (int j = 0; j < 4; j++) {
            float m0 = xl[j].x + xr[j].x + ep[j].x;
            float m1 = xl[j].y + xr[j].y + ep[j].y;
            float m2 = xl[j].z + xr[j].z + ep[j].z;
            float m3 = xl[j].w + xr[j].w + ep[j].w;
            // leaky_relu slope 0.2
            m0 = fmaxf(m0, 0.f) + 0.2f * fminf(m0, 0.f);
            m1 = fmaxf(m1, 0.f) + 0.2f * fminf(m1, 0.f);
            m2 = fmaxf(m2, 0.f) + 0.2f * fminf(m2, 0.f);
            m3 = fmaxf(m3, 0.f) + 0.2f * fminf(m3, 0.f);

            float p = fmaf(m0, at4.x, fmaf(m1, at4.y, fmaf(m2, at4.z, m3 * at4.w)));
            // 8-lane segmented reduce -> per-head logit
            p += __shfl_xor_sync(0xffffffffu, p, 4);
            p += __shfl_xor_sync(0xffffffffu, p, 2);
            p += __shfl_xor_sync(0xffffffffu, p, 1);

            // No max-subtraction: |logit| bounded (~12), exp safe in fp32;
            // exp(l)/sum(exp(l)) == softmax exactly.
            const float ev = __expf(p);

            float* dst = g_agg + (size_t)rr[j] * HD + c0;
            asm volatile("red.global.add.v4.f32 [%0], {%1, %2, %3, %4};"
                         :: "l"(dst), "f"(xl[j].x * ev), "f"(xl[j].y * ev),
                            "f"(xl[j].z * ev), "f"(xl[j].w * ev)
                         : "memory");
            if ((ln & 7) == 0)
                atomicAdd(&g_sum[(size_t)rr[j] * HEADS + h], ev);
        }
    }
}

// ---------------- finalize: normalize + head mean ---------------------------
__global__ void finalize_kernel(float* __restrict__ out, int N) {
    int i = blockIdx.x * blockDim.x + threadIdx.x;   // over N * 32
    if (i >= N * D_OUT) return;
    int n = i >> 5, d = i & 31;
    const float* a = g_agg + (size_t)n * HD + d;
    const float* sm = g_sum + (size_t)n * HEADS;
    float v = a[0]  / (sm[0] + 1e-8f)
            + a[32] / (sm[1] + 1e-8f)
            + a[64] / (sm[2] + 1e-8f)
            + a[96] / (sm[3] + 1e-8f);
    out[i] = 0.25f * v;
}

// ---------------- launch -----------------------------------------------------
extern "C" void kernel_launch(void* const* d_in, const int* in_sizes, int n_in,
                              void* d_out, int out_size)
{
    const float* nodes = (const float*)d_in[0];
    const int*   snd   = (const int*)  d_in[1];
    const int*   rcv   = (const int*)  d_in[2];
    const float* eattr = (const float*)d_in[3];
    // Defend against the n_node scalar being present (size-1 input) or absent.
    int wbase = (in_sizes[4] == 1) ? 5 : 4;
    const float* Wl   = (const float*)d_in[wbase + 0];
    const float* Wr   = (const float*)d_in[wbase + 1];
    const float* We   = (const float*)d_in[wbase + 2];
    const float* attn = (const float*)d_in[wbase + 3];

    const int N = in_sizes[0] / F_IN;
    const int E = in_sizes[1];

    zero_kernel<<<(N * HD + 255) / 256, 256>>>(N * HD, N * HEADS);

    dim3 gg((N + BM - 1) / BM, 4);
    gemm_kernel<<<gg, 256>>>(nodes, Wl, Wr, N);

    // persistent grid: 8 blocks/SM * 148 SMs, 4 edges per warp-iteration
    edge_fused_kernel<<<1184, 256>>>(snd, rcv, eattr, We, attn, E);
    finalize_kernel<<<(N * D_OUT + 255) / 256, 256>>>((float*)d_out, N);
}

// round 8
// speedup vs baseline: 1.8899x; 1.1136x over previous
#include <cuda_runtime.h>
#include <cuda_bf16.h>
#include <cstdint>

// Problem constants (shapes fixed by the dataset)
#define N_NODE   50000
#define N_EDGE   800000
#define F_IN     128
#define EDGE_DIM 16
#define HEADS    4
#define D_OUT    32
#define HD       (HEADS * D_OUT)   // 128

// ---------------- scratch (device globals; no runtime allocation) ----------
__device__ float g_xl [(size_t)N_NODE * HD];     // 25.6 MB
__device__ float g_xr [(size_t)N_NODE * HD];     // 25.6 MB
__device__ float g_sum[(size_t)N_NODE * HEADS];  //  0.8 MB
__device__ float g_agg[(size_t)N_NODE * HD];     // 25.6 MB

// ---------------- zero init (vectorized) ------------------------------------
__global__ void zero_kernel(int n4_agg, int n4_sum) {
    int i = blockIdx.x * blockDim.x + threadIdx.x;
    const float4 z = make_float4(0.f, 0.f, 0.f, 0.f);
    if (i < n4_agg)               ((float4*)g_agg)[i] = z;
    else if (i - n4_agg < n4_sum) ((float4*)g_sum)[i - n4_agg] = z;
}

// ---------------- projection GEMM: x_l / x_r = nodes @ W ------------------
// C[M,128] = A[M,128] @ W[128,128], two weight matrices via blockIdx.y.
// 128x64 tile, BK=16, 256 threads, 8x4 microtile.
#define BM 128
#define BN 64
#define BK 16
__global__ __launch_bounds__(256) void gemm_kernel(
    const float* __restrict__ A,
    const float* __restrict__ Wl,
    const float* __restrict__ Wr,
    int M)
{
    const int byi = blockIdx.y;                 // 0..3
    const float* B = (byi < 2) ? Wl : Wr;
    float*       C = (byi < 2) ? g_xl : g_xr;
    const int cn0 = (byi & 1) * BN;
    const int rm0 = blockIdx.x * BM;

    __shared__ float As[BK][BM + 4];            // transposed, padded
    __shared__ float Bs[BK][BN];

    float acc[8][4];
#pragma unroll
    for (int i = 0; i < 8; i++)
#pragma unroll
        for (int j = 0; j < 4; j++) acc[i][j] = 0.f;

    const int tid = threadIdx.x;
    const int tx = tid & 15;                    // col group (4 cols)
    const int ty = tid >> 4;                    // row group (8 rows)

    // A loads: 128 rows x 16 k = 512 float4; thread t does rows t/4 and t/4+64
    const int ar = tid >> 2;                    // 0..63
    const int ak = (tid & 3) * 4;               // 0,4,8,12
    // B loads: 16 k x 64 cols = 256 float4; one per thread
    const int bk = tid >> 4;                    // 0..15
    const int bj = (tid & 15) * 4;

    for (int k0 = 0; k0 < F_IN; k0 += BK) {
#pragma unroll
        for (int half = 0; half < 2; half++) {
            const int row = ar + half * 64;
            float4 av = make_float4(0.f, 0.f, 0.f, 0.f);
            if (rm0 + row < M)
                av = *(const float4*)&A[(size_t)(rm0 + row) * F_IN + k0 + ak];
            As[ak][row]     = av.x;
            As[ak + 1][row] = av.y;
            As[ak + 2][row] = av.z;
            As[ak + 3][row] = av.w;
        }
        float4 bv = *(const float4*)&B[(size_t)(k0 + bk) * HD + cn0 + bj];
        *(float4*)&Bs[bk][bj] = bv;
        __syncthreads();
#pragma unroll
        for (int k = 0; k < BK; k++) {
            float4 ra0 = *(const float4*)&As[k][ty * 8];
            float4 ra1 = *(const float4*)&As[k][ty * 8 + 4];
            float4 rb  = *(const float4*)&Bs[k][tx * 4];
            float a_[8] = {ra0.x, ra0.y, ra0.z, ra0.w,
                           ra1.x, ra1.y, ra1.z, ra1.w};
            float b_[4] = {rb.x, rb.y, rb.z, rb.w};
#pragma unroll
            for (int i = 0; i < 8; i++)
#pragma unroll
                for (int j = 0; j < 4; j++)
                    acc[i][j] = fmaf(a_[i], b_[j], acc[i][j]);
        }
        __syncthreads();
    }
#pragma unroll
    for (int i = 0; i < 8; i++) {
        int r = rm0 + ty * 8 + i;
        if (r < M) {
            float4 v = make_float4(acc[i][0], acc[i][1], acc[i][2], acc[i][3]);
            *(float4*)&C[(size_t)r * HD + cn0 + tx * 4] = v;
        }
    }
}

// ---------------- fused edge pass: 4 edges/warp, amortized smem weights ----
// (unchanged from round 7 — measured at ~170us, near its L2 floor)
__global__ __launch_bounds__(256) void edge_fused_kernel(
    const int*   __restrict__ snd,
    const int*   __restrict__ rcv,
    const float* __restrict__ eattr,
    const float* __restrict__ We,
    const float* __restrict__ attn,
    int E)
{
    __shared__ float we_s[EDGE_DIM * HD];  // 8 KB
    __shared__ float at_s[HD];
    const int tid = threadIdx.x;
    for (int i = tid; i < EDGE_DIM * HD; i += 256) we_s[i] = We[i];
    if (tid < HD) at_s[tid] = attn[tid];
    __syncthreads();

    const int ln = tid & 31;
    const int c0 = ln * 4;
    const int h  = ln >> 3;
    const float4 at4 = *(const float4*)&at_s[c0];

    const int warps_total = gridDim.x * (blockDim.x >> 5);
    const int warp_id = blockIdx.x * (blockDim.x >> 5) + (tid >> 5);

    for (int e0 = warp_id * 4; e0 < E; e0 += warps_total * 4) {
        // 4 consecutive edges (E is a multiple of 4; e0 is 16B-aligned)
        const int4 s4 = *(const int4*)&snd[e0];
        const int4 r4 = *(const int4*)&rcv[e0];
        const int ss[4] = {s4.x, s4.y, s4.z, s4.w};
        const int rr[4] = {r4.x, r4.y, r4.z, r4.w};

        // cooperative edge-feature load: 4 edges x 16 dims = 64 floats,
        // lane ln gets float2 at flat offset 2*ln (edge = ln/8, dim = 2ln%16)
        const float2 myea = *(const float2*)&eattr[(size_t)e0 * EDGE_DIM + 2 * ln];

        // gathers (the dominant memory cost; 4 independent -> good MLP)
        float4 xl[4], xr[4];
#pragma unroll
        for (int j = 0; j < 4; j++) {
            xl[j] = *(const float4*)(g_xl + (size_t)ss[j] * HD + c0);
            xr[j] = *(const float4*)(g_xr + (size_t)rr[j] * HD + c0);
        }

        // edge projection: one weight load per k, reused across 4 edges
        float4 ep[4];
#pragma unroll
        for (int j = 0; j < 4; j++) ep[j] = make_float4(0.f, 0.f, 0.f, 0.f);
#pragma unroll
        for (int k = 0; k < EDGE_DIM; k++) {
            const float4 w = *(const float4*)&we_s[k * HD + c0];
#pragma unroll
            for (int j = 0; j < 4; j++) {
                const int src = j * 8 + (k >> 1);
                const float a = (k & 1)
                    ? __shfl_sync(0xffffffffu, myea.y, src)
                    : __shfl_sync(0xffffffffu, myea.x, src);
                ep[j].x = fmaf(a, w.x, ep[j].x);
                ep[j].y = fmaf(a, w.y, ep[j].y);
                ep[j].z = fmaf(a, w.z, ep[j].z);
                ep[j].w = fmaf(a, w.w, ep[j].w);
            }
        }

#pragma unroll
        for (int j = 0; j < 4; j++) {
            float m0 = xl[j].x + xr[j].x + ep[j].x;
            float m1 = xl[j].y + xr[j].y + ep[j].y;
            float m2 = xl[j].z + xr[j].z + ep[j].z;
            float m3 = xl[j].w + xr[j].w + ep[j].w;
            // leaky_relu slope 0.2
            m0 = fmaxf(m0, 0.f) + 0.2f * fminf(m0, 0.f);
            m1 = fmaxf(m1, 0.f) + 0.2f * fminf(m1, 0.f);
            m2 = fmaxf(m2, 0.f) + 0.2f * fminf(m2, 0.f);
            m3 = fmaxf(m3, 0.f) + 0.2f * fminf(m3, 0.f);

            float p = fmaf(m0, at4.x, fmaf(m1, at4.y, fmaf(m2, at4.z, m3 * at4.w)));
            // 8-lane segmented reduce -> per-head logit
            p += __shfl_xor_sync(0xffffffffu, p, 4);
            p += __shfl_xor_sync(0xffffffffu, p, 2);
            p += __shfl_xor_sync(0xffffffffu, p, 1);

            // No max-subtraction: |logit| bounded (~12), exp safe in fp32;
            // exp(l)/sum(exp(l)) == softmax exactly.
            const float ev = __expf(p);

            float* dst = g_agg + (size_t)rr[j] * HD + c0;
            asm volatile("red.global.add.v4.f32 [%0], {%1, %2, %3, %4};"
                         :: "l"(dst), "f"(xl[j].x * ev), "f"(xl[j].y * ev),
                            "f"(xl[j].z * ev), "f"(xl[j].w * ev)
                         : "memory");
            if ((ln & 7) == 0)
                atomicAdd(&g_sum[(size_t)rr[j] * HEADS + h], ev);
        }
    }
}

// ---------------- finalize: normalize + head mean (vectorized) --------------
// Thread i handles node n = i/8, dims c..c+3 where c = (i%8)*4.
__global__ void finalize_kernel(float* __restrict__ out, int N) {
    int i = blockIdx.x * blockDim.x + threadIdx.x;   // over N * 8
    if (i >= N * 8) return;
    const int n = i >> 3;
    const int c = (i & 7) * 4;
    const float* a = g_agg + (size_t)n * HD + c;
    const float4 s4 = *(const float4*)(g_sum + (size_t)n * HEADS);
    const float4 a0 = *(const float4*)(a);
    const float4 a1 = *(const float4*)(a + 32);
    const float4 a2 = *(const float4*)(a + 64);
    const float4 a3 = *(const float4*)(a + 96);
    const float i0 = 0.25f / (s4.x + 1e-8f);
    const float i1 = 0.25f / (s4.y + 1e-8f);
    const float i2 = 0.25f / (s4.z + 1e-8f);
    const float i3 = 0.25f / (s4.w + 1e-8f);
    float4 o;
    o.x = a0.x * i0 + a1.x * i1 + a2.x * i2 + a3.x * i3;
    o.y = a0.y * i0 + a1.y * i1 + a2.y * i2 + a3.y * i3;
    o.z = a0.z * i0 + a1.z * i1 + a2.z * i2 + a3.z * i3;
    o.w = a0.w * i0 + a1.w * i1 + a2.w * i2 + a3.w * i3;
    *(float4*)&out[(size_t)n * D_OUT + c] = o;
}

// ---------------- launch -----------------------------------------------------
extern "C" void kernel_launch(void* const* d_in, const int* in_sizes, int n_in,
                              void* d_out, int out_size)
{
    const float* nodes = (const float*)d_in[0];
    const int*   snd   = (const int*)  d_in[1];
    const int*   rcv   = (const int*)  d_in[2];
    const float* eattr = (const float*)d_in[3];
    // Defend against the n_node scalar being present (size-1 input) or absent.
    int wbase = (in_sizes[4] == 1) ? 5 : 4;
    const float* Wl   = (const float*)d_in[wbase + 0];
    const float* Wr   = (const float*)d_in[wbase + 1];
    const float* We   = (const float*)d_in[wbase + 2];
    const float* attn = (const float*)d_in[wbase + 3];

    const int N = in_sizes[0] / F_IN;
    const int E = in_sizes[1];

    const int n4_agg = N * HD / 4;
    const int n4_sum = N * HEADS / 4;
    zero_kernel<<<(n4_agg + n4_sum + 255) / 256, 256>>>(n4_agg, n4_sum);

    dim3 gg((N + BM - 1) / BM, 4);
    gemm_kernel<<<gg, 256>>>(nodes, Wl, Wr, N);

    // persistent grid: 8 blocks/SM * 148 SMs, 4 edges per warp-iteration
    edge_fused_kernel<<<1184, 256>>>(snd, rcv, eattr, We, attn, E);
    finalize_kernel<<<(N * 8 + 255) / 256, 256>>>((float*)d_out, N);
}